// round 1
// baseline (speedup 1.0000x reference)
#include <cuda_runtime.h>
#include <cuda_fp16.h>

#define NMAX 4194304
#define CN 10

// ---------------- device globals (scratch; no allocations allowed) ----------
static __device__ double   g_ce;
static __device__ double   g_fo;
static __device__ unsigned g_umin;
static __device__ unsigned g_umax;
static __device__ int      g_label;
static __device__ int      g_swap;
static __device__ double   g_hist[96];          // [(b*2+acc)*2 + {0:wc,1:wu}], b in [0,21]
static __device__ float2   g_rec[NMAX];         // .x = unc (sign bit = !acc), .y = half2(wc,wu)

// ---------------- fast math (FFMA-only, no MUFU) ----------------------------
__device__ __forceinline__ float fast_logf(float a) {
    // natural log for normal positive a; max err ~1e-6 (degree-5 log1p minimax on [-1/3,1/3])
    int   e = (__float_as_int(a) - 0x3f2aaaab) & 0xff800000;
    float m = __int_as_float(__float_as_int(a) - e);
    float i = (float)e * 1.19209290e-7f;
    float f = m - 1.0f;
    float s = f * f;
    float r = fmaf(0.230836749f, f, -0.279208571f);
    float t = fmaf(0.331826031f, f, -0.498910338f);
    r = fmaf(r, s, t);
    r = fmaf(r, s, f);
    r = fmaf(i, 0.693147182f, r);
    return r;
}

__device__ __forceinline__ float fast_expf(float a) {
    // e^a for a in ~[-40, 40] with normal result; ~1 ulp core accuracy
    float j  = fmaf(1.442695041f, a, 12582912.0f);
    int   ji = __float_as_int(j) - 0x4B400000;
    j = j - 12582912.0f;
    float f = fmaf(j, -0.693145752f, a);
    f = fmaf(j, -1.42860677e-6f, f);
    float r = 1.37805939e-3f;
    r = fmaf(r, f, 8.37312452e-3f);
    r = fmaf(r, f, 4.16695364e-2f);
    r = fmaf(r, f, 1.66665524e-1f);
    r = fmaf(r, f, 4.99999851e-1f);
    r = fmaf(r, f, 1.00000000e+0f);
    r = fmaf(r, f, 1.00000000e+0f);
    return __int_as_float(__float_as_int(r) + (ji << 23));
}

// ---------------- kernel 0: reset accumulators, detect input order, label ---
__global__ void kinit(const float* __restrict__ a, const float* __restrict__ b) {
    if (threadIdx.x == 0) {
        g_ce = 0.0; g_fo = 0.0;
        g_umin = 0x7f800000u;   // +inf bits
        g_umax = 0u;            // +0 bits
        bool onehot = true;
        #pragma unroll
        for (int c = 0; c < CN; c++) {
            float v = b[c];
            if (v != 0.0f && v != 1.0f) onehot = false;
        }
        const float* Y = onehot ? b : a;
        g_swap = onehot ? 0 : 1;
        // flattened argmax of one-hot y == label of sample 0 (first occurrence of max)
        float best = Y[0]; int arg = 0;
        #pragma unroll
        for (int c = 1; c < CN; c++) { float v = Y[c]; if (v > best) { best = v; arg = c; } }
        g_label = arg;
    }
    if (threadIdx.x < 96) g_hist[threadIdx.x] = 0.0;
}

// ---------------- pass 1: per-sample entropy / weights / ce / focal ---------
#define P1_THREADS 256
#define P1_ITERS   8

__global__ void __launch_bounds__(P1_THREADS) pass1(const float* __restrict__ in0,
                                                    const float* __restrict__ in1,
                                                    int n) {
    const float* P = in0;
    const float* Y = in1;
    if (g_swap) { P = in1; Y = in0; }
    const int label = g_label;

    float ceS = 0.0f, foS = 0.0f;
    float umn = 3.402823466e38f, umx = 0.0f;

    int base = blockIdx.x * (P1_THREADS * P1_ITERS);

    #pragma unroll 1
    for (int k = 0; k < P1_ITERS; k++) {
        int i = base + k * P1_THREADS + threadIdx.x;
        if (i >= n) break;
        const float2* pr = reinterpret_cast<const float2*>(P) + (size_t)i * 5;
        const float2* yr = reinterpret_cast<const float2*>(Y) + (size_t)i * 5;
        float2 P0 = pr[0], P1v = pr[1], P2 = pr[2], P3 = pr[3], P4 = pr[4];
        float2 Y0 = yr[0], Y1 = yr[1], Y2 = yr[2], Y3 = yr[3], Y4 = yr[4];
        float p[CN]  = {P0.x, P0.y, P1v.x, P1v.y, P2.x, P2.y, P3.x, P3.y, P4.x, P4.y};
        float yy[CN] = {Y0.x, Y0.y, Y1.x, Y1.y, Y2.x, Y2.y, Y3.x, Y3.y, Y4.x, Y4.y};

        float ent = 0.0f, A = 0.0f, B = 0.0f;
        float best = p[0]; int arg = 0;
        #pragma unroll
        for (int c = 0; c < CN; c++) {
            float pk  = p[c];
            float lpe = fast_logf(fmaxf(pk, 1e-10f));               // EPS clamp (entropy)
            float lpf = (pk >= 1e-8f) ? lpe : -18.420680744f;       // FOCAL_EPS clamp
            ent = fmaf(pk, lpe, ent);
            float yl = yy[c] * lpf;
            A += yl;                       // sum y*logp
            B = fmaf(yl, pk, B);           // sum y*logp*p
            if (c > 0 && pk > best) { best = pk; arg = c; }          // first-occurrence argmax
        }
        float unc = -ent;                  // >= 0
        ceS += -A;                         // ce_per
        foS += (B - A);                    // focal_per = -sum y*logp*(1-p)
        umn = fminf(umn, unc);
        umx = fmaxf(umx, unc);

        // ---- soft_T(e) with temp=0.01 (hard step; saturated almost always) ----
        float e   = unc * 0.43429448190325176f;                      // unc / ln(10)
        float num = e * 0.9f;
        float den = fmaxf((1.0f - e) * 0.1f, 1e-10f);
        float x   = 100.0f * (fast_logf(fmaxf(num, 1e-37f)) - fast_logf(den));
        float s;
        if (x >= 17.0f)       s = 1.0f;    // 1/(1+e^-x) rounds to 1.0f
        else if (x <= -25.0f) s = 0.0f;    // contribution < 1.4e-11
        else                  s = __fdividef(1.0f, 1.0f + fast_expf(-x));

        // ---- tanh(unc), unc in [0, ln10] ----
        float em = fast_expf(-2.0f * unc);
        float t  = __fdividef(1.0f - em, 1.0f + em);

        float wc = (1.0f - s) * (1.0f - t);
        float wu = s * t;
        int   acc = (arg == label);

        float2 rec;
        rec.x = __int_as_float(__float_as_int(unc) | (acc ? 0 : 0x80000000));
        __half2 h = __floats2half2_rn(wc, wu);
        rec.y = __uint_as_float(*reinterpret_cast<unsigned*>(&h));
        g_rec[i] = rec;
    }

    // ---- block reduction -> one double atomic each ----
    #pragma unroll
    for (int o = 16; o; o >>= 1) {
        ceS += __shfl_xor_sync(0xffffffffu, ceS, o);
        foS += __shfl_xor_sync(0xffffffffu, foS, o);
        umn = fminf(umn, __shfl_xor_sync(0xffffffffu, umn, o));
        umx = fmaxf(umx, __shfl_xor_sync(0xffffffffu, umx, o));
    }
    __shared__ float rC[8], rF[8], rMn[8], rMx[8];
    int w = threadIdx.x >> 5, l = threadIdx.x & 31;
    if (l == 0) { rC[w] = ceS; rF[w] = foS; rMn[w] = umn; rMx[w] = umx; }
    __syncthreads();
    if (threadIdx.x == 0) {
        float c = rC[0], f = rF[0], mn = rMn[0], mx = rMx[0];
        #pragma unroll
        for (int q = 1; q < P1_THREADS / 32; q++) {
            c += rC[q]; f += rF[q]; mn = fminf(mn, rMn[q]); mx = fmaxf(mx, rMx[q]);
        }
        atomicAdd(&g_ce, (double)c);
        atomicAdd(&g_fo, (double)f);
        atomicMin(&g_umin, __float_as_uint(mn));   // unc >= 0: uint order == float order
        atomicMax(&g_umax, __float_as_uint(mx));
    }
}

// ---------------- pass 2: threshold binning into per-thread shared hists ----
#define P2_THREADS 128
#define P2_STRIDE  89   // 88 entries padded; 89 coprime with 32 banks

__global__ void __launch_bounds__(P2_THREADS) pass2(int n) {
    __shared__ float sh[P2_THREADS * P2_STRIDE];
    int base = threadIdx.x * P2_STRIDE;
    #pragma unroll
    for (int k = 0; k < P2_STRIDE; k++) sh[base + k] = 0.0f;
    __syncthreads();

    float umin  = __uint_as_float(g_umin);
    float umax  = __uint_as_float(g_umax);
    float range = umax - umin;
    float th[21];
    #pragma unroll
    for (int j = 0; j < 21; j++) {
        float tl = (j == 20) ? 1.0f : 0.05f * (float)j;
        th[j] = fmaf(tl, range, umin);
    }

    for (int i = blockIdx.x * P2_THREADS + threadIdx.x; i < n; i += gridDim.x * P2_THREADS) {
        float2 rec = g_rec[i];
        int   bits = __float_as_int(rec.x);
        int   acc  = (bits >> 31) ? 0 : 1;
        float unc  = fabsf(rec.x);
        unsigned hv = __float_as_uint(rec.y);
        __half2  h  = *reinterpret_cast<__half2*>(&hv);
        float wc = __low2float(h);
        float wu = __high2float(h);
        int b = 0;
        #pragma unroll
        for (int j = 0; j < 21; j++) b += (unc > th[j]) ? 1 : 0;   // b in [0,21]
        int key = (b * 2 + acc) * 2;
        sh[base + key]     += wc;
        sh[base + key + 1] += wu;
    }
    __syncthreads();

    if (threadIdx.x < 88) {
        float sum = 0.0f;
        #pragma unroll 4
        for (int t = 0; t < P2_THREADS; t++) sum += sh[t * P2_STRIDE + threadIdx.x];
        if (sum != 0.0f) atomicAdd(&g_hist[threadIdx.x], (double)sum);
    }
}

// ---------------- finalize: avu curve, trapezoid AUC, outputs ---------------
__global__ void kfinal(float* __restrict__ out, double inv_n) {
    if (threadIdx.x == 0) {
        double totAU = 0.0, totIU = 0.0;
        for (int b = 0; b < 22; b++) {
            totAU += g_hist[(b * 2 + 1) * 2 + 1];
            totIU += g_hist[(b * 2 + 0) * 2 + 1];
        }
        double preAC = 0.0, preIC = 0.0, preAU = 0.0, preIU = 0.0;
        double auc = 0.0, prev = 0.0, prev_tl = 0.0;
        for (int j = 0; j < 21; j++) {
            preAC += g_hist[(j * 2 + 1) * 2 + 0];
            preIC += g_hist[(j * 2 + 0) * 2 + 0];
            preAU += g_hist[(j * 2 + 1) * 2 + 1];
            preIU += g_hist[(j * 2 + 0) * 2 + 1];
            double nac = preAC, nic = preIC;
            double nau = totAU - preAU, niu = totIU - preIU;
            double avu = (nac + niu) / (nac + nau + nic + niu + 1e-10);
            double tl  = (j == 20) ? 1.0 : (double)(0.05f * (float)j);
            if (j > 0) auc += (avu + prev) * 0.5 * (tl - prev_tl);
            prev = avu; prev_tl = tl;
        }
        double focal = g_fo * inv_n;
        double ce    = g_ce * inv_n;
        double savu  = -log(fmax(auc, 1e-10)) + focal;
        out[0] = (float)savu;
        out[1] = (float)ce;
    }
}

// ---------------- launcher --------------------------------------------------
extern "C" void kernel_launch(void* const* d_in, const int* in_sizes, int n_in,
                              void* d_out, int out_size) {
    const float* in0 = (const float*)d_in[0];
    const float* in1 = (const float*)d_in[1];
    int n = in_sizes[0] / CN;
    if (n > NMAX) n = NMAX;

    kinit<<<1, 96>>>(in0, in1);

    int b1 = (n + P1_THREADS * P1_ITERS - 1) / (P1_THREADS * P1_ITERS);
    pass1<<<b1, P1_THREADS>>>(in0, in1, n);

    pass2<<<1480, P2_THREADS>>>(n);

    kfinal<<<1, 32>>>((float*)d_out, 1.0 / (double)n);
}

// round 2
// speedup vs baseline: 1.1908x; 1.1908x over previous
#include <cuda_runtime.h>
#include <cuda_fp16.h>

#define NMAX 4194304
#define CN 10

// ---------------- device globals --------------------------------------------
struct GAcc {
    double   ce, fo;                 // 16 B
    unsigned umaxb, uminneg;         // max(unc bits), max(~unc bits)  (zero-init neutral)
    unsigned ticket, pad;            // last-block-done ticket
    double   hist[88];               // [(b*2+acc)*2 + {0:wc,1:wu}], b in [0,21]
};
static __device__ GAcc   g;
static __device__ float2 g_rec[NMAX];   // .x = unc (sign bit = !acc), .y = half2(wc,wu)

// ---------------- fast math (FFMA-only, no MUFU) ----------------------------
__device__ __forceinline__ float fast_logf(float a) {
    int   e = (__float_as_int(a) - 0x3f2aaaab) & 0xff800000;
    float m = __int_as_float(__float_as_int(a) - e);
    float i = (float)e * 1.19209290e-7f;
    float f = m - 1.0f;
    float s = f * f;
    float r = fmaf(0.230836749f, f, -0.279208571f);
    float t = fmaf(0.331826031f, f, -0.498910338f);
    r = fmaf(r, s, t);
    r = fmaf(r, s, f);
    r = fmaf(i, 0.693147182f, r);
    return r;
}

__device__ __forceinline__ float fast_expf(float a) {
    float j  = fmaf(1.442695041f, a, 12582912.0f);
    int   ji = __float_as_int(j) - 0x4B400000;
    j = j - 12582912.0f;
    float f = fmaf(j, -0.693145752f, a);
    f = fmaf(j, -1.42860677e-6f, f);
    float r = 1.37805939e-3f;
    r = fmaf(r, f, 8.37312452e-3f);
    r = fmaf(r, f, 4.16695364e-2f);
    r = fmaf(r, f, 1.66665524e-1f);
    r = fmaf(r, f, 4.99999851e-1f);
    r = fmaf(r, f, 1.00000000e+0f);
    r = fmaf(r, f, 1.00000000e+0f);
    return __int_as_float(__float_as_int(r) + (ji << 23));
}

// ---------------- kernel 0: zero the accumulator struct ---------------------
__global__ void zeroK() {
    unsigned* w = reinterpret_cast<unsigned*>(&g);
    for (int i = threadIdx.x; i < (int)(sizeof(GAcc) / 4); i += blockDim.x) w[i] = 0u;
}

// ---------------- pass 1 ----------------------------------------------------
#define P1_T 256
#define P1_I 4

__device__ __forceinline__ void proc_sample(const float* p, const float* yy, int label,
                                            float& ceS, float& foS, float& umn, float& umx,
                                            float2& rec) {
    float ent = 0.0f, A = 0.0f, B = 0.0f;
    float best = p[0]; int arg = 0;
    #pragma unroll
    for (int c = 0; c < CN; c++) {
        float pk  = p[c];
        float lpe = fast_logf(fmaxf(pk, 1e-10f));             // EPS clamp (entropy)
        float lpf = (pk >= 1e-8f) ? lpe : -18.420680744f;     // FOCAL_EPS clamp
        ent = fmaf(pk, lpe, ent);
        float yl = yy[c] * lpf;
        A += yl;                                              // sum y*logp
        B = fmaf(yl, pk, B);                                  // sum y*logp*p
        if (c > 0 && pk > best) { best = pk; arg = c; }       // first-occurrence argmax
    }
    float unc = fmaxf(-ent, 0.0f);
    ceS += -A;
    foS += (B - A);
    umn = fminf(umn, unc);
    umx = fmaxf(umx, unc);

    // soft_T with temp=0.01: hard step; compare-based short circuit (no logs)
    float e   = unc * 0.43429448190325176f;                   // unc / ln(10)
    float num = e * 0.9f;
    float den = fmaxf((1.0f - e) * 0.1f, 1e-10f);
    float s;
    if (num >= 1.18546522f * den) {            // x >= 17  -> sigmoid rounds to 1.0f
        s = 1.0f;
    } else if (num <= 0.77880078f * den) {     // x <= -25 -> contribution < 1.4e-11
        s = 0.0f;
    } else {
        float x = 100.0f * (fast_logf(fmaxf(num, 1e-37f)) - fast_logf(den));
        s = __fdividef(1.0f, 1.0f + fast_expf(-x));
    }
    float em = fast_expf(-2.0f * unc);
    float t  = __fdividef(1.0f - em, 1.0f + em);              // tanh(unc)

    float wc = (1.0f - s) * (1.0f - t);
    float wu = s * t;
    int   acc = (arg == label);

    rec.x = __int_as_float(__float_as_int(unc) | (acc ? 0 : 0x80000000));
    __half2 h = __floats2half2_rn(wc, wu);
    rec.y = __uint_as_float(*reinterpret_cast<unsigned*>(&h));
}

__global__ void __launch_bounds__(P1_T) pass1(const float* __restrict__ in0,
                                              const float* __restrict__ in1, int n) {
    __shared__ int s_label, s_swap;
    __shared__ float rC[P1_T / 32], rF[P1_T / 32], rMn[P1_T / 32], rMx[P1_T / 32];

    if (threadIdx.x == 0) {
        bool onehot = true;
        #pragma unroll
        for (int c = 0; c < CN; c++) { float v = in1[c]; if (v != 0.0f && v != 1.0f) onehot = false; }
        const float* Y = onehot ? in1 : in0;
        s_swap = onehot ? 0 : 1;
        float best = Y[0]; int arg = 0;
        #pragma unroll
        for (int c = 1; c < CN; c++) { float v = Y[c]; if (v > best) { best = v; arg = c; } }
        s_label = arg;
    }
    __syncthreads();
    const int swap = s_swap;
    const float4* P4 = reinterpret_cast<const float4*>(swap ? in1 : in0);
    const float4* Y4 = reinterpret_cast<const float4*>(swap ? in0 : in1);
    const int label = s_label;

    float ceS = 0.0f, foS = 0.0f;
    float umn = 3.402823466e38f, umx = 0.0f;

    const int npair = n >> 1;
    int base = blockIdx.x * (P1_T * P1_I);

    #pragma unroll 1
    for (int k = 0; k < P1_I; k++) {
        int pr = base + k * P1_T + threadIdx.x;
        if (pr >= npair) break;
        // 2 samples = 80 B = 5 aligned float4 per tensor
        float v[20], w[20];
        #pragma unroll
        for (int j = 0; j < 5; j++) {
            float4 a = __ldcs(P4 + (size_t)pr * 5 + j);
            float4 b = __ldcs(Y4 + (size_t)pr * 5 + j);
            v[4 * j + 0] = a.x; v[4 * j + 1] = a.y; v[4 * j + 2] = a.z; v[4 * j + 3] = a.w;
            w[4 * j + 0] = b.x; w[4 * j + 1] = b.y; w[4 * j + 2] = b.z; w[4 * j + 3] = b.w;
        }
        float2 r0, r1;
        proc_sample(v,      w,      label, ceS, foS, umn, umx, r0);
        proc_sample(v + 10, w + 10, label, ceS, foS, umn, umx, r1);
        float4 out4; out4.x = r0.x; out4.y = r0.y; out4.z = r1.x; out4.w = r1.y;
        reinterpret_cast<float4*>(g_rec)[pr] = out4;
    }

    // odd-n tail: block 0 / thread 0 handles the last sample
    if ((n & 1) && blockIdx.x == 0 && threadIdx.x == 0) {
        int i = n - 1;
        const float* P = swap ? in1 : in0;
        const float* Y = swap ? in0 : in1;
        float v[CN], w[CN];
        #pragma unroll
        for (int c = 0; c < CN; c++) { v[c] = P[(size_t)i * CN + c]; w[c] = Y[(size_t)i * CN + c]; }
        float2 r;
        proc_sample(v, w, label, ceS, foS, umn, umx, r);
        g_rec[i] = r;
    }

    // block reduction -> one atomic each
    #pragma unroll
    for (int o = 16; o; o >>= 1) {
        ceS += __shfl_xor_sync(0xffffffffu, ceS, o);
        foS += __shfl_xor_sync(0xffffffffu, foS, o);
        umn = fminf(umn, __shfl_xor_sync(0xffffffffu, umn, o));
        umx = fmaxf(umx, __shfl_xor_sync(0xffffffffu, umx, o));
    }
    int wid = threadIdx.x >> 5, lid = threadIdx.x & 31;
    if (lid == 0) { rC[wid] = ceS; rF[wid] = foS; rMn[wid] = umn; rMx[wid] = umx; }
    __syncthreads();
    if (threadIdx.x == 0) {
        float c = rC[0], f = rF[0], mn = rMn[0], mx = rMx[0];
        #pragma unroll
        for (int q = 1; q < P1_T / 32; q++) {
            c += rC[q]; f += rF[q]; mn = fminf(mn, rMn[q]); mx = fmaxf(mx, rMx[q]);
        }
        atomicAdd(&g.ce, (double)c);
        atomicAdd(&g.fo, (double)f);
        atomicMax(&g.umaxb, __float_as_uint(mx));        // unc >= 0: uint order == float order
        atomicMax(&g.uminneg, ~__float_as_uint(mn));     // min via max of complement
    }
}

// ---------------- pass 2: binning + inline finalize -------------------------
#define P2_T 128
#define P2_S 89          // 88 entries padded; 89 coprime with 32 banks
#define P2_GRID 592

__device__ __forceinline__ void hist_one(float* base, float2 rec, const float* th) {
    int   bits = __float_as_int(rec.x);
    int   acc  = (bits < 0) ? 0 : 1;
    float unc  = fabsf(rec.x);
    unsigned hv = __float_as_uint(rec.y);
    __half2  h  = *reinterpret_cast<__half2*>(&hv);
    float wc = __low2float(h);
    float wu = __high2float(h);
    int b = 0;
    #pragma unroll
    for (int j = 0; j < 21; j++) b += (unc > th[j]) ? 1 : 0;      // b in [0,21]
    int key = (b * 2 + acc) * 2;
    base[key]     += wc;
    base[key + 1] += wu;
}

__global__ void __launch_bounds__(P2_T) pass2(int n, float* __restrict__ out) {
    __shared__ float sh[P2_T * P2_S];
    float* base = sh + threadIdx.x * P2_S;
    #pragma unroll
    for (int k = 0; k < P2_S; k++) base[k] = 0.0f;
    __syncthreads();

    float umin  = __uint_as_float(~g.uminneg);
    float umax  = __uint_as_float(g.umaxb);
    float range = umax - umin;
    float th[21];
    #pragma unroll
    for (int j = 0; j < 21; j++) {
        float tl = (j == 20) ? 1.0f : 0.05f * (float)j;
        th[j] = fmaf(tl, range, umin);
    }

    const int npair = n >> 1;
    const float4* rec4 = reinterpret_cast<const float4*>(g_rec);
    for (int pr = blockIdx.x * P2_T + threadIdx.x; pr < npair; pr += P2_GRID * P2_T) {
        float4 q = rec4[pr];
        float2 a; a.x = q.x; a.y = q.y;
        float2 b; b.x = q.z; b.y = q.w;
        hist_one(base, a, th);
        hist_one(base, b, th);
    }
    if ((n & 1) && blockIdx.x == 0 && threadIdx.x == 0) hist_one(base, g_rec[n - 1], th);
    __syncthreads();

    if (threadIdx.x < 88) {
        float sum = 0.0f;
        #pragma unroll 4
        for (int t = 0; t < P2_T; t++) sum += sh[t * P2_S + threadIdx.x];
        if (sum != 0.0f) atomicAdd(&g.hist[threadIdx.x], (double)sum);
    }
    __threadfence();
    __syncthreads();

    if (threadIdx.x == 0) {
        unsigned tk = atomicAdd(&g.ticket, 1u);
        if (tk == P2_GRID - 1) {
            // ---- finalize (float math; runs once) ----
            float h[88];
            #pragma unroll 4
            for (int i = 0; i < 88; i++) h[i] = (float)g.hist[i];
            float totAU = 0.0f, totIU = 0.0f;
            #pragma unroll
            for (int b = 0; b < 22; b++) { totAU += h[4 * b + 3]; totIU += h[4 * b + 1]; }
            float pAC = 0.0f, pIC = 0.0f, pAU = 0.0f, pIU = 0.0f;
            float auc = 0.0f, prev = 0.0f, prev_tl = 0.0f;
            #pragma unroll 1
            for (int j = 0; j < 21; j++) {
                pAC += h[4 * j + 2];
                pIC += h[4 * j + 0];
                pAU += h[4 * j + 3];
                pIU += h[4 * j + 1];
                float nau = totAU - pAU, niu = totIU - pIU;
                float avu = (pAC + niu) / (pAC + nau + pIC + niu + 1e-10f);
                float tl  = (j == 20) ? 1.0f : 0.05f * (float)j;
                if (j > 0) auc += (avu + prev) * 0.5f * (tl - prev_tl);
                prev = avu; prev_tl = tl;
            }
            double dn    = 1.0 / (double)n;
            float  focal = (float)(g.fo * dn);
            float  ce    = (float)(g.ce * dn);
            out[0] = -logf(fmaxf(auc, 1e-10f)) + focal;
            out[1] = ce;
        }
    }
}

// ---------------- launcher --------------------------------------------------
extern "C" void kernel_launch(void* const* d_in, const int* in_sizes, int n_in,
                              void* d_out, int out_size) {
    const float* in0 = (const float*)d_in[0];
    const float* in1 = (const float*)d_in[1];
    int n = in_sizes[0] / CN;
    if (n > NMAX) n = NMAX;

    zeroK<<<1, 256>>>();

    int npair = n >> 1;
    int b1 = (npair + P1_T * P1_I - 1) / (P1_T * P1_I);
    if (b1 < 1) b1 = 1;
    pass1<<<b1, P1_T>>>(in0, in1, n);

    pass2<<<P2_GRID, P2_T>>>(n, (float*)d_out);
}